// round 1
// baseline (speedup 1.0000x reference)
#include <cuda_runtime.h>
#include <cuda_bf16.h>

// Problem constants (static per reference)
#define BS 4
#define H0 64
#define W0 64
#define L0 (H0 * W0)            // 4096
#define ANCHOR_NUM 64
#define CELLS (BS * L0)         // 16384

// Scratch: winner match-index per grid cell (-1 = empty).
// Last-write-wins scatter semantics == max match index wins.
__device__ int g_winner[CELLS];

__global__ void ae_init_kernel() {
    int i = blockIdx.x * blockDim.x + threadIdx.x;
    if (i < CELLS) g_winner[i] = -1;
}

__global__ void ae_scatter_kernel(const int* __restrict__ b_ids,
                                  const int* __restrict__ i_ids,
                                  int M) {
    int m = blockIdx.x * blockDim.x + threadIdx.x;
    if (m < M) {
        int b = b_ids[m];
        int i = i_ids[m];
        atomicMax(&g_winner[b * L0 + i], m);
    }
}

// One block (1024 threads) per batch. Each thread owns 4 consecutive cells.
// 1) stage conf values into shared
// 2) compute NMS mask (cell >= right, down, down-right neighbors; pad = 0)
// 3) block-wide exclusive scan over mask counts -> raster-order ranks
// 4) first min(cnt,64) true cells -> shared list; threads 0..63 emit anchors
__global__ void __launch_bounds__(1024, 1)
ae_anchor_kernel(const float* __restrict__ mconf,
                 const int* __restrict__ j_ids,
                 float* __restrict__ out_anchors) {
    __shared__ float conf_s[L0];
    __shared__ int   list_s[ANCHOR_NUM];
    __shared__ int   warp_sums[32];
    __shared__ int   total_s;

    const int b    = blockIdx.x;
    const int t    = threadIdx.x;
    const int base = b * L0;

    // Stage conf grid (resolve winners -> mconf)
#pragma unroll
    for (int k = 0; k < 4; k++) {
        int c  = t * 4 + k;
        int wn = g_winner[base + c];
        conf_s[c] = (wn >= 0) ? mconf[wn] : 0.0f;
    }
    __syncthreads();

    // NMS mask for my 4 cells
    int mbits = 0;
    int cnt_loc = 0;
#pragma unroll
    for (int k = 0; k < 4; k++) {
        int c = t * 4 + k;
        int h = c >> 6;
        int w = c & 63;
        float v = conf_s[c];
        float r  = (w < W0 - 1)                 ? conf_s[c + 1]      : 0.0f;
        float d  = (h < H0 - 1)                 ? conf_s[c + W0]     : 0.0f;
        float dr = (w < W0 - 1 && h < H0 - 1)   ? conf_s[c + W0 + 1] : 0.0f;
        bool m = (v > 0.0f) && (v >= r) && (v >= d) && (v >= dr);
        mbits |= ((int)m) << k;
        cnt_loc += (int)m;
    }

    // Block-wide scan of cnt_loc (1024 threads = exactly 32 warps)
    const int lane = t & 31;
    const int wid  = t >> 5;
    int x = cnt_loc;
#pragma unroll
    for (int o = 1; o < 32; o <<= 1) {
        int y = __shfl_up_sync(0xFFFFFFFFu, x, o);
        if (lane >= o) x += y;
    }
    if (lane == 31) warp_sums[wid] = x;  // inclusive warp totals
    __syncthreads();
    if (wid == 0) {
        int s = warp_sums[lane];
#pragma unroll
        for (int o = 1; o < 32; o <<= 1) {
            int y = __shfl_up_sync(0xFFFFFFFFu, s, o);
            if (lane >= o) s += y;
        }
        warp_sums[lane] = s;             // inclusive scan of warp totals
        if (lane == 31) total_s = s;     // grand total
    }
    __syncthreads();

    int excl = (x - cnt_loc) + (wid > 0 ? warp_sums[wid - 1] : 0);

    // Record the first ANCHOR_NUM true cells in raster order
#pragma unroll
    for (int k = 0; k < 4; k++) {
        if (mbits & (1 << k)) {
            if (excl < ANCHOR_NUM) list_s[excl] = t * 4 + k;
            excl++;
        }
    }
    __syncthreads();

    const int cnt = total_s;
    if (t < ANCHOR_NUM) {
        float4 a = make_float4(0.0f, 0.0f, 0.0f, 0.0f);
        if (cnt > 0) {
            // arange(64) % cnt; when cnt>=64 this is just t (< 64 stored entries)
            int idx = t % cnt;           // idx < min(cnt, 64) in all cases
            int sel = list_s[idx];
            int j   = j_ids[g_winner[base + sel]];
            a.x = (float)(sel >> 6);     // i // W0
            a.y = (float)(sel & 63);     // i %  W0
            a.z = (float)(j >> 6);       // j // W1
            a.w = (float)(j & 63);       // j %  W1
        }
        reinterpret_cast<float4*>(out_anchors)[b * ANCHOR_NUM + t] = a;
    }
}

extern "C" void kernel_launch(void* const* d_in, const int* in_sizes, int n_in,
                              void* d_out, int out_size) {
    const float* conf  = (const float*)d_in[0];   // [BS, L0, L1]
    const float* mconf = (const float*)d_in[1];   // [M]
    const int*   b_ids = (const int*)d_in[2];     // [M]
    const int*   i_ids = (const int*)d_in[3];     // [M]
    const int*   j_ids = (const int*)d_in[4];     // [M]
    float* out = (float*)d_out;

    const int M     = in_sizes[1];
    const int nconf = in_sizes[0];
    // Output layout: anchors [BS*64*2*2] first, then conf_matrix passthrough.
    const int anchors_elems = out_size - nconf;   // expected 1024

    // Bulk passthrough copy first (dominates; D2D memcpy hits the LTS cap)
    cudaMemcpyAsync(out + anchors_elems, conf, (size_t)nconf * sizeof(float),
                    cudaMemcpyDeviceToDevice, 0);

    ae_init_kernel<<<(CELLS + 1023) / 1024, 1024>>>();
    ae_scatter_kernel<<<(M + 255) / 256, 256>>>(b_ids, i_ids, M);
    ae_anchor_kernel<<<BS, 1024>>>(mconf, j_ids, out);
}

// round 2
// speedup vs baseline: 1.1169x; 1.1169x over previous
#include <cuda_runtime.h>
#include <cuda_bf16.h>

// Problem constants (static per reference)
#define BS 4
#define H0 64
#define W0 64
#define L0 (H0 * W0)            // 4096
#define ANCHOR_NUM 64

#define NUM_COPY_BLOCKS 2048
#define THREADS 1024

// Fused kernel:
//   blocks 0..BS-1      : per-batch anchor extraction (scatter + NMS + select)
//   blocks BS..BS+NCB-1 : float4 grid-stride passthrough copy of conf_matrix
__global__ void __launch_bounds__(THREADS, 1)
ae_fused_kernel(const float*  __restrict__ conf,
                const float*  __restrict__ mconf,
                const int*    __restrict__ b_ids,
                const int*    __restrict__ i_ids,
                const int*    __restrict__ j_ids,
                float*        __restrict__ out,
                int nconf, int M, int anchors_elems) {
    const int t = threadIdx.x;

    if (blockIdx.x >= BS) {
        // ---------------- bulk copy path ----------------
        const int cb = blockIdx.x - BS;
        const long long n4 = (long long)nconf >> 2;         // float4 count
        const float4* __restrict__ src = (const float4*)conf;
        float4* __restrict__ dst = (float4*)(out + anchors_elems);
        long long idx = (long long)cb * THREADS + t;
        const long long stride = (long long)NUM_COPY_BLOCKS * THREADS;
        for (; idx < n4; idx += stride)
            dst[idx] = src[idx];
        return;
    }

    // ---------------- anchor path (block b) ----------------
    __shared__ int   win_s[L0];          // winner match index per cell (-1 empty)
    __shared__ float conf_s[L0];
    __shared__ int   list_s[ANCHOR_NUM];
    __shared__ int   warp_sums[32];
    __shared__ int   total_s;

    const int b = blockIdx.x;

    // init winners
#pragma unroll
    for (int k = 0; k < 4; k++) win_s[t * 4 + k] = -1;
    __syncthreads();

    // private scatter: last-write-wins == max match index wins
    for (int m = t; m < M; m += THREADS) {
        if (b_ids[m] == b)
            atomicMax(&win_s[i_ids[m]], m);
    }
    __syncthreads();

    // stage confidences
#pragma unroll
    for (int k = 0; k < 4; k++) {
        int c  = t * 4 + k;
        int wn = win_s[c];
        conf_s[c] = (wn >= 0) ? mconf[wn] : 0.0f;
    }
    __syncthreads();

    // NMS mask: local max vs right/down/down-right (pad = 0), conf > 0
    int mbits = 0, cnt_loc = 0;
#pragma unroll
    for (int k = 0; k < 4; k++) {
        int c = t * 4 + k;
        int h = c >> 6;
        int w = c & 63;
        float v  = conf_s[c];
        float r  = (w < W0 - 1)               ? conf_s[c + 1]      : 0.0f;
        float d  = (h < H0 - 1)               ? conf_s[c + W0]     : 0.0f;
        float dr = (w < W0 - 1 && h < H0 - 1) ? conf_s[c + W0 + 1] : 0.0f;
        bool mm = (v > 0.0f) && (v >= r) && (v >= d) && (v >= dr);
        mbits |= ((int)mm) << k;
        cnt_loc += (int)mm;
    }

    // block-wide inclusive scan over per-thread counts (32 warps exactly)
    const int lane = t & 31;
    const int wid  = t >> 5;
    int x = cnt_loc;
#pragma unroll
    for (int o = 1; o < 32; o <<= 1) {
        int y = __shfl_up_sync(0xFFFFFFFFu, x, o);
        if (lane >= o) x += y;
    }
    if (lane == 31) warp_sums[wid] = x;
    __syncthreads();
    if (wid == 0) {
        int s = warp_sums[lane];
#pragma unroll
        for (int o = 1; o < 32; o <<= 1) {
            int y = __shfl_up_sync(0xFFFFFFFFu, s, o);
            if (lane >= o) s += y;
        }
        warp_sums[lane] = s;
        if (lane == 31) total_s = s;
    }
    __syncthreads();

    int excl = (x - cnt_loc) + (wid > 0 ? warp_sums[wid - 1] : 0);

    // first ANCHOR_NUM surviving cells in raster order
#pragma unroll
    for (int k = 0; k < 4; k++) {
        if (mbits & (1 << k)) {
            if (excl < ANCHOR_NUM) list_s[excl] = t * 4 + k;
            excl++;
        }
    }
    __syncthreads();

    const int cnt = total_s;
    if (t < ANCHOR_NUM) {
        float4 a = make_float4(0.0f, 0.0f, 0.0f, 0.0f);
        if (cnt > 0) {
            int idx = t % cnt;               // arange(64) % cnt
            int sel = list_s[idx];
            int j   = j_ids[win_s[sel]];
            a.x = (float)(sel >> 6);
            a.y = (float)(sel & 63);
            a.z = (float)(j >> 6);
            a.w = (float)(j & 63);
        }
        reinterpret_cast<float4*>(out)[b * ANCHOR_NUM + t] = a;
    }
}

extern "C" void kernel_launch(void* const* d_in, const int* in_sizes, int n_in,
                              void* d_out, int out_size) {
    const float* conf  = (const float*)d_in[0];   // [BS, L0, L1]
    const float* mconf = (const float*)d_in[1];   // [M]
    const int*   b_ids = (const int*)d_in[2];     // [M]
    const int*   i_ids = (const int*)d_in[3];     // [M]
    const int*   j_ids = (const int*)d_in[4];     // [M]
    float* out = (float*)d_out;

    const int nconf = in_sizes[0];
    const int M     = in_sizes[1];
    const int anchors_elems = out_size - nconf;   // expected 1024

    ae_fused_kernel<<<BS + NUM_COPY_BLOCKS, THREADS>>>(
        conf, mconf, b_ids, i_ids, j_ids, out, nconf, M, anchors_elems);
}

// round 3
// speedup vs baseline: 1.1270x; 1.0090x over previous
#include <cuda_runtime.h>
#include <cuda_bf16.h>

// Problem constants (static per reference)
#define BS 4
#define H0 64
#define W0 64
#define L0 (H0 * W0)            // 4096
#define ANCHOR_NUM 64

#define NUM_COPY_BLOCKS 2048
#define THREADS 1024

__device__ __forceinline__ float4 ldcs4(const float4* p) {
    float4 v;
    asm volatile("ld.global.cs.v4.f32 {%0,%1,%2,%3}, [%4];"
                 : "=f"(v.x), "=f"(v.y), "=f"(v.z), "=f"(v.w) : "l"(p));
    return v;
}
__device__ __forceinline__ void stcs4(float4* p, float4 v) {
    asm volatile("st.global.cs.v4.f32 [%0], {%1,%2,%3,%4};"
                 :: "l"(p), "f"(v.x), "f"(v.y), "f"(v.z), "f"(v.w) : "memory");
}

// Fused kernel:
//   blocks 0..BS-1      : per-batch anchor extraction (scatter + NMS + select)
//   blocks BS..BS+NCB-1 : float4 streaming passthrough copy of conf_matrix
__global__ void __launch_bounds__(THREADS, 1)
ae_fused_kernel(const float*  __restrict__ conf,
                const float*  __restrict__ mconf,
                const int*    __restrict__ b_ids,
                const int*    __restrict__ i_ids,
                const int*    __restrict__ j_ids,
                float*        __restrict__ out,
                int nconf, int M, int anchors_elems) {
    const int t = threadIdx.x;

    if (blockIdx.x >= BS) {
        // ---------------- bulk copy path ----------------
        const int cb = blockIdx.x - BS;
        const long long n4 = (long long)nconf >> 2;          // float4 count
        const float4* __restrict__ src = (const float4*)conf;
        float4* __restrict__ dst = (float4*)(out + anchors_elems);
        const long long stride = (long long)NUM_COPY_BLOCKS * THREADS;
        long long idx = (long long)cb * THREADS + t;

        if (n4 == stride * 8) {
            // exact fit: batch 8 LDG.128 (deep MLP) then 8 STG.128
            float4 v0 = ldcs4(src + idx);
            float4 v1 = ldcs4(src + idx + stride);
            float4 v2 = ldcs4(src + idx + stride * 2);
            float4 v3 = ldcs4(src + idx + stride * 3);
            float4 v4 = ldcs4(src + idx + stride * 4);
            float4 v5 = ldcs4(src + idx + stride * 5);
            float4 v6 = ldcs4(src + idx + stride * 6);
            float4 v7 = ldcs4(src + idx + stride * 7);
            stcs4(dst + idx,              v0);
            stcs4(dst + idx + stride,     v1);
            stcs4(dst + idx + stride * 2, v2);
            stcs4(dst + idx + stride * 3, v3);
            stcs4(dst + idx + stride * 4, v4);
            stcs4(dst + idx + stride * 5, v5);
            stcs4(dst + idx + stride * 6, v6);
            stcs4(dst + idx + stride * 7, v7);
        } else {
            for (; idx < n4; idx += stride)
                stcs4(dst + idx, ldcs4(src + idx));
        }
        return;
    }

    // ---------------- anchor path (block b) ----------------
    __shared__ int   win_s[L0];          // winner match index per cell (-1 empty)
    __shared__ float conf_s[L0];
    __shared__ int   list_s[ANCHOR_NUM];
    __shared__ int   warp_sums[32];
    __shared__ int   total_s;

    const int b = blockIdx.x;

    // init winners
#pragma unroll
    for (int k = 0; k < 4; k++) win_s[t * 4 + k] = -1;
    __syncthreads();

    // private scatter: last-write-wins == max match index wins
    for (int m = t; m < M; m += THREADS) {
        if (b_ids[m] == b)
            atomicMax(&win_s[i_ids[m]], m);
    }
    __syncthreads();

    // stage confidences
#pragma unroll
    for (int k = 0; k < 4; k++) {
        int c  = t * 4 + k;
        int wn = win_s[c];
        conf_s[c] = (wn >= 0) ? mconf[wn] : 0.0f;
    }
    __syncthreads();

    // NMS mask: local max vs right/down/down-right (pad = 0), conf > 0
    int mbits = 0, cnt_loc = 0;
#pragma unroll
    for (int k = 0; k < 4; k++) {
        int c = t * 4 + k;
        int h = c >> 6;
        int w = c & 63;
        float v  = conf_s[c];
        float r  = (w < W0 - 1)               ? conf_s[c + 1]      : 0.0f;
        float d  = (h < H0 - 1)               ? conf_s[c + W0]     : 0.0f;
        float dr = (w < W0 - 1 && h < H0 - 1) ? conf_s[c + W0 + 1] : 0.0f;
        bool mm = (v > 0.0f) && (v >= r) && (v >= d) && (v >= dr);
        mbits |= ((int)mm) << k;
        cnt_loc += (int)mm;
    }

    // block-wide inclusive scan over per-thread counts (32 warps exactly)
    const int lane = t & 31;
    const int wid  = t >> 5;
    int x = cnt_loc;
#pragma unroll
    for (int o = 1; o < 32; o <<= 1) {
        int y = __shfl_up_sync(0xFFFFFFFFu, x, o);
        if (lane >= o) x += y;
    }
    if (lane == 31) warp_sums[wid] = x;
    __syncthreads();
    if (wid == 0) {
        int s = warp_sums[lane];
#pragma unroll
        for (int o = 1; o < 32; o <<= 1) {
            int y = __shfl_up_sync(0xFFFFFFFFu, s, o);
            if (lane >= o) s += y;
        }
        warp_sums[lane] = s;
        if (lane == 31) total_s = s;
    }
    __syncthreads();

    int excl = (x - cnt_loc) + (wid > 0 ? warp_sums[wid - 1] : 0);

    // first ANCHOR_NUM surviving cells in raster order
#pragma unroll
    for (int k = 0; k < 4; k++) {
        if (mbits & (1 << k)) {
            if (excl < ANCHOR_NUM) list_s[excl] = t * 4 + k;
            excl++;
        }
    }
    __syncthreads();

    const int cnt = total_s;
    if (t < ANCHOR_NUM) {
        float4 a = make_float4(0.0f, 0.0f, 0.0f, 0.0f);
        if (cnt > 0) {
            int idx = t % cnt;               // arange(64) % cnt
            int sel = list_s[idx];
            int j   = j_ids[win_s[sel]];
            a.x = (float)(sel >> 6);
            a.y = (float)(sel & 63);
            a.z = (float)(j >> 6);
            a.w = (float)(j & 63);
        }
        reinterpret_cast<float4*>(out)[b * ANCHOR_NUM + t] = a;
    }
}

extern "C" void kernel_launch(void* const* d_in, const int* in_sizes, int n_in,
                              void* d_out, int out_size) {
    const float* conf  = (const float*)d_in[0];   // [BS, L0, L1]
    const float* mconf = (const float*)d_in[1];   // [M]
    const int*   b_ids = (const int*)d_in[2];     // [M]
    const int*   i_ids = (const int*)d_in[3];     // [M]
    const int*   j_ids = (const int*)d_in[4];     // [M]
    float* out = (float*)d_out;

    const int nconf = in_sizes[0];
    const int M     = in_sizes[1];
    const int anchors_elems = out_size - nconf;   // expected 1024

    ae_fused_kernel<<<BS + NUM_COPY_BLOCKS, THREADS>>>(
        conf, mconf, b_ids, i_ids, j_ids, out, nconf, M, anchors_elems);
}